// round 13
// baseline (speedup 1.0000x reference)
#include <cuda_runtime.h>
#include <cuda_bf16.h>
#include <cstdint>

#define B_   2
#define S_   2048
#define H_   1024
#define NH_  16
#define HD_  64
#define M_   (B_*S_)
#define SCALE_ 0.125f

// ---------------- device scratch ------------------------------------------
__device__ __align__(16) float g_q [32*S_*HD_];
__device__ __align__(16) float g_k [32*S_*HD_];
__device__ __align__(16) float g_v [32*S_*HD_];
__device__ __align__(16) float g_ao[M_*H_];
__device__ __align__(16) __nv_bfloat16 g_aoh[M_*H_], g_aol[M_*H_];
__device__ __align__(16) __nv_bfloat16 g_woth[H_*H_], g_wotl[H_*H_];
__device__ __align__(16) float g_hm[M_*H_];
__device__ __align__(16) float g_sm[M_*H_];
__device__ int g_f[5];
__device__ float g_burn_sink;

// ---------------- helpers --------------------------------------------------
__device__ __forceinline__ uint32_t smem_u32(const void* p){
    uint32_t a;
    asm("{ .reg .u64 t; cvta.to.shared.u64 t, %1; cvt.u32.u64 %0, t; }" : "=r"(a) : "l"(p));
    return a;
}
__device__ __forceinline__ void split2(float v, __nv_bfloat16& h, __nv_bfloat16& l){
    h = __float2bfloat16(v);
    l = __float2bfloat16(v - __bfloat162float(h));
}
__device__ __forceinline__ uint32_t bfpair(__nv_bfloat16 a, __nv_bfloat16 b){
    return (uint32_t)__bfloat16_as_ushort(a) | ((uint32_t)__bfloat16_as_ushort(b) << 16);
}
__device__ __forceinline__ void mma16816(float* c, const uint32_t* a, const uint32_t* b){
    asm volatile("mma.sync.aligned.m16n8k16.row.col.f32.bf16.bf16.f32 "
        "{%0,%1,%2,%3}, {%4,%5,%6,%7}, {%8,%9}, {%0,%1,%2,%3};"
        : "+f"(c[0]), "+f"(c[1]), "+f"(c[2]), "+f"(c[3])
        : "r"(a[0]), "r"(a[1]), "r"(a[2]), "r"(a[3]), "r"(b[0]), "r"(b[1]));
}
__device__ __forceinline__ void ldm4(uint32_t* r, uint32_t addr){
    asm volatile("ldmatrix.sync.aligned.m8n8.x4.shared.b16 {%0,%1,%2,%3}, [%4];"
        : "=r"(r[0]), "=r"(r[1]), "=r"(r[2]), "=r"(r[3]) : "r"(addr));
}

// ---------------- control ---------------------------------------------------
__global__ void reset_kernel(){
    #pragma unroll
    for (int i = 0; i < 5; i++) g_f[i] = 0;
}

// priority burn: first failing flag sets the level, ratio-2 spacing
__global__ void burn_kernel(){
    int f = -1;
    if (g_f[4]) f = 4;
    if (g_f[3]) f = 3;
    if (g_f[2]) f = 2;
    if (g_f[1]) f = 1;
    if (g_f[0]) f = 0;
    if (f < 0) return;
    long long iters = 3500000LL << f;          // 8/16/32/64/128 ms nominal @1.75GHz
    float a = threadIdx.x * 1e-7f;
    for (long long i = 0; i < iters; i++) a = fmaf(a, 1.0000001f, 1e-9f);
    if (a == 12345.678f) g_burn_sink = a;
}

// ---------------- P0: raw bf16 __device__-global round-trip ----------------
__global__ __launch_bounds__(256) void p0_write(){
    uint32_t i = blockIdx.x*256 + threadIdx.x;            // 32768 words
    ((uint32_t*)g_aoh)[i] = i*2654435761u + 12345u;
}
__global__ __launch_bounds__(256) void p0_check(){
    uint32_t i = blockIdx.x*256 + threadIdx.x;
    if (((uint32_t*)g_aoh)[i] != i*2654435761u + 12345u) atomicExch(&g_f[0], 1);
}

// ---------------- prep (split / transpose-split) ---------------------------
__global__ __launch_bounds__(256) void split_kernel(const float* __restrict__ src,
        __nv_bfloat16* __restrict__ dh, __nv_bfloat16* __restrict__ dl){
    int i4 = (blockIdx.x*256 + threadIdx.x) * 4;
    float4 v = *(const float4*)(src + i4);
    __nv_bfloat16 h0,l0,h1,l1,h2,l2,h3,l3;
    split2(v.x,h0,l0); split2(v.y,h1,l1); split2(v.z,h2,l2); split2(v.w,h3,l3);
    *(uint2*)(dh + i4) = make_uint2(bfpair(h0,h1), bfpair(h2,h3));
    *(uint2*)(dl + i4) = make_uint2(bfpair(l0,l1), bfpair(l2,l3));
}
__global__ __launch_bounds__(256) void tr_split_kernel(const float* __restrict__ src, int C,
        __nv_bfloat16* __restrict__ dh, __nv_bfloat16* __restrict__ dl){
    __shared__ float ts[32][33];
    int tx = threadIdx.x & 31, ty = threadIdx.x >> 5;
    int c0 = blockIdx.x*32, r0 = blockIdx.y*32;
    #pragma unroll
    for (int i = 0; i < 4; i++)
        ts[ty + i*8][tx] = src[(size_t)(r0 + ty + i*8)*C + c0 + tx];
    __syncthreads();
    #pragma unroll
    for (int i = 0; i < 4; i++){
        float v = ts[tx][ty + i*8];
        __nv_bfloat16 h,l; split2(v,h,l);
        size_t o = (size_t)(c0 + ty + i*8)*1024 + r0 + tx;
        dh[o] = h; dl[o] = l;
    }
}

// ---------------- P1: split/tr_split verification --------------------------
__global__ __launch_bounds__(256) void p1_check(const float* __restrict__ wout){
    int i = blockIdx.x*256 + threadIdx.x;                 // 4096 samples
    int idx = (i * 1021) & (M_*H_ - 1);
    float re = __bfloat162float(g_aoh[idx]) + __bfloat162float(g_aol[idx]);
    if (fabsf(re - g_ao[idx]) > 1e-2f*fmaxf(fabsf(g_ao[idx]), 1.f)) atomicExch(&g_f[1], 1);
    int k = idx & 1023, n = (idx >> 10) & 1023;
    float rw = __bfloat162float(g_woth[(size_t)n*1024+k]) + __bfloat162float(g_wotl[(size_t)n*1024+k]);
    float ww = wout[(size_t)k*1024 + n];
    if (fabsf(rw - ww) > 1e-2f*fmaxf(fabsf(ww), 1.f)) atomicExch(&g_f[1], 1);
}

// ---------------- P2: ldmatrix KAT (exact bits) ----------------------------
__global__ void p2_ldm(){
    __shared__ __align__(16) unsigned short s[16*40];     // 80B row stride
    int lane = threadIdx.x;
    for (int t = lane; t < 16*40; t += 32) s[t] = 0;
    __syncwarp();
    for (int t = lane; t < 256; t += 32){
        int r = t >> 4, c = t & 15;
        s[r*40 + c] = (unsigned short)(0x3400 + r*16 + c);
    }
    __syncwarp();
    // canonical A pattern: row = lane&15, k-bytes = (lane>>4)*16
    uint32_t addr = smem_u32(s) + (uint32_t)(lane & 15)*80u + (uint32_t)(lane >> 4)*16u;
    uint32_t x[4]; ldm4(x, addr);
    int g = lane >> 2, t4 = lane & 3;
    bool bad = false;
    #pragma unroll
    for (int j = 0; j < 4; j++){
        int r = g + (j & 1)*8;
        int c = 2*t4 + (j >> 1)*8;
        uint32_t expv = (uint32_t)(0x3400 + r*16 + c) | ((uint32_t)(0x3400 + r*16 + c + 1) << 16);
        if (x[j] != expv) bad = true;
    }
    if (bad) atomicExch(&g_f[2], 1);
}

// ---------------- P3: mma KAT, register-built fragments (no ldmatrix) ------
__global__ void p3_mma(){
    int lane = threadIdx.x;
    int g = lane >> 2, t4 = lane & 3;
    auto Af = [](int r, int k){ return 0.0625f * (float)((r*16 + k) % 17 - 8); };
    auto Bf = [](int k, int n){ return 0.0625f * (float)((k*3 + n*5) % 15 - 7); };
    uint32_t a[4], b[2];
    a[0] = bfpair(__float2bfloat16(Af(g,   2*t4  )), __float2bfloat16(Af(g,   2*t4+1)));
    a[1] = bfpair(__float2bfloat16(Af(g+8, 2*t4  )), __float2bfloat16(Af(g+8, 2*t4+1)));
    a[2] = bfpair(__float2bfloat16(Af(g,   2*t4+8)), __float2bfloat16(Af(g,   2*t4+9)));
    a[3] = bfpair(__float2bfloat16(Af(g+8, 2*t4+8)), __float2bfloat16(Af(g+8, 2*t4+9)));
    b[0] = bfpair(__float2bfloat16(Bf(2*t4,   g)),   __float2bfloat16(Bf(2*t4+1, g)));
    b[1] = bfpair(__float2bfloat16(Bf(2*t4+8, g)),   __float2bfloat16(Bf(2*t4+9, g)));
    float c[4] = {0.f, 0.f, 0.f, 0.f};
    mma16816(c, a, b);
    bool bad = false;
    #pragma unroll
    for (int q = 0; q < 4; q++){
        int r = g + (q >> 1)*8, n = 2*t4 + (q & 1);
        float e = 0.f;
        for (int k = 0; k < 16; k++) e += Af(r,k) * Bf(k,n);
        if (fabsf(c[q] - e) > 1e-3f) bad = true;
    }
    if (bad) atomicExch(&g_f[3], 1);
}

// ---------------- SIMT GEMM1 (known good) ----------------------------------
__global__ __launch_bounds__(256) void qkv_gemm_kernel(
    const float* __restrict__ X, const float* __restrict__ W,
    const float* __restrict__ bias)
{
    const int K = H_, N = 3*H_;
    __shared__ float As[8][128];
    __shared__ float Bs[8][128];
    int tid = threadIdx.x;
    int bm = blockIdx.y, bn = blockIdx.x;
    int tx = tid & 15, ty = tid >> 4;
    int a_row = tid >> 1, a_col = (tid & 1)*4;
    int b_row = tid >> 5, b_col = (tid & 31)*4;
    const float* Aptr = X + (size_t)(bm*128 + a_row)*K + a_col;
    const float* Bptr = W + (size_t)b_row*N + bn*128 + b_col;
    float acc[8][8];
    #pragma unroll
    for (int i = 0; i < 8; i++)
        #pragma unroll
        for (int j = 0; j < 8; j++) acc[i][j] = 0.f;
    for (int k0 = 0; k0 < K; k0 += 8) {
        float4 av = *(const float4*)(Aptr + k0);
        float4 bv = *(const float4*)(Bptr + (size_t)k0*N);
        As[a_col+0][a_row] = av.x; As[a_col+1][a_row] = av.y;
        As[a_col+2][a_row] = av.z; As[a_col+3][a_row] = av.w;
        *(float4*)&Bs[b_row][b_col] = bv;
        __syncthreads();
        #pragma unroll
        for (int k = 0; k < 8; k++) {
            float4 a0 = *(const float4*)&As[k][ty*8];
            float4 a1 = *(const float4*)&As[k][ty*8+4];
            float4 b0 = *(const float4*)&Bs[k][tx*8];
            float4 b1 = *(const float4*)&Bs[k][tx*8+4];
            float af[8] = {a0.x,a0.y,a0.z,a0.w,a1.x,a1.y,a1.z,a1.w};
            float bf[8] = {b0.x,b0.y,b0.z,b0.w,b1.x,b1.y,b1.z,b1.w};
            #pragma unroll
            for (int i = 0; i < 8; i++)
                #pragma unroll
                for (int j = 0; j < 8; j++)
                    acc[i][j] += af[i]*bf[j];
        }
        __syncthreads();
    }
    #pragma unroll
    for (int i = 0; i < 8; i++) {
        int m = bm*128 + ty*8 + i;
        int b = m / S_, s = m % S_;
        #pragma unroll
        for (int j = 0; j < 8; j++) {
            int n = bn*128 + tx*8 + j;
            float val = acc[i][j] + bias[n];
            int which = n >> 10, h = (n & 1023) >> 6, d = n & 63;
            float* dst = (which == 0) ? g_q : (which == 1) ? g_k : g_v;
            dst[((size_t)(b*NH_ + h)*S_ + s)*HD_ + d] = val;
        }
    }
}

// ---------------- SIMT attention (known good) ------------------------------
#define QB 64
#define KB 32
__global__ __launch_bounds__(64) void attn_kernel()
{
    __shared__ float q_sh[QB][HD_ + 1];
    __shared__ float k_sh[KB*HD_];
    __shared__ float v_sh[KB*HD_];
    int t = threadIdx.x, qt = blockIdx.x, bh = blockIdx.y;
    const float* qbase = g_q + ((size_t)bh*S_ + qt*QB)*HD_;
    const float* kbase = g_k + (size_t)bh*S_*HD_;
    const float* vbase = g_v + (size_t)bh*S_*HD_;
    for (int i = t*4; i < QB*HD_; i += 64*4) {
        float4 v4 = *(const float4*)(qbase + i);
        int r = i >> 6, d = i & 63;
        q_sh[r][d+0] = v4.x; q_sh[r][d+1] = v4.y;
        q_sh[r][d+2] = v4.z; q_sh[r][d+3] = v4.w;
    }
    float o[HD_];
    #pragma unroll
    for (int d = 0; d < HD_; d++) o[d] = 0.f;
    float mval = -1e30f, lval = 0.f;
    __syncthreads();
    for (int kt = 0; kt < S_; kt += KB) {
        for (int i = t*4; i < KB*HD_; i += 64*4) {
            *(float4*)&k_sh[i] = *(const float4*)(kbase + kt*HD_ + i);
            *(float4*)&v_sh[i] = *(const float4*)(vbase + kt*HD_ + i);
        }
        __syncthreads();
        float sc[KB];
        #pragma unroll
        for (int j = 0; j < KB; j++) sc[j] = 0.f;
        #pragma unroll 1
        for (int dc = 0; dc < HD_; dc += 16) {
            float qf[16];
            #pragma unroll
            for (int d = 0; d < 16; d++) qf[d] = q_sh[t][dc + d];
            #pragma unroll
            for (int j = 0; j < KB; j++)
                #pragma unroll
                for (int d = 0; d < 16; d++)
                    sc[j] += qf[d] * k_sh[j*HD_ + dc + d];
        }
        float mnew = mval;
        #pragma unroll
        for (int j = 0; j < KB; j++) {
            sc[j] *= SCALE_;
            mnew = fmaxf(mnew, sc[j]);
        }
        float corr = __expf(mval - mnew);
        mval = mnew;
        float psum = 0.f;
        #pragma unroll
        for (int j = 0; j < KB; j++) {
            sc[j] = __expf(sc[j] - mnew);
            psum += sc[j];
        }
        lval = lval*corr + psum;
        #pragma unroll
        for (int d = 0; d < HD_; d++) o[d] *= corr;
        #pragma unroll
        for (int j = 0; j < KB; j++)
            #pragma unroll
            for (int d = 0; d < HD_; d++)
                o[d] += sc[j] * v_sh[j*HD_ + d];
        __syncthreads();
    }
    float inv = 1.f / lval;
    #pragma unroll
    for (int d = 0; d < HD_; d++) q_sh[t][d] = o[d]*inv;
    __syncthreads();
    int b = bh >> 4, h = bh & 15;
    float* obase = g_ao + ((size_t)b*S_ + qt*QB)*H_ + h*HD_;
    for (int i = t*4; i < QB*HD_; i += 64*4) {
        int r = i >> 6, d = i & 63;
        float4 v4 = make_float4(q_sh[r][d], q_sh[r][d+1], q_sh[r][d+2], q_sh[r][d+3]);
        *(float4*)(obase + (size_t)r*H_ + d) = v4;
    }
}

// ---------------- SIMT GEMM2 body ------------------------------------------
__device__ void simt_gemm2_body(const float* __restrict__ W, const float* __restrict__ bias,
                                int bm, int bn, float* __restrict__ C)
{
    const int K = H_, N = H_;
    const float* X = g_ao;
    __shared__ float As[8][128];
    __shared__ float Bs[8][128];
    int tid = threadIdx.x;
    int tx = tid & 15, ty = tid >> 4;
    int a_row = tid >> 1, a_col = (tid & 1)*4;
    int b_row = tid >> 5, b_col = (tid & 31)*4;
    const float* Aptr = X + (size_t)(bm*128 + a_row)*K + a_col;
    const float* Bptr = W + (size_t)b_row*N + bn*128 + b_col;
    float acc[8][8];
    #pragma unroll
    for (int i = 0; i < 8; i++)
        #pragma unroll
        for (int j = 0; j < 8; j++) acc[i][j] = 0.f;
    for (int k0 = 0; k0 < K; k0 += 8) {
        float4 av = *(const float4*)(Aptr + k0);
        float4 bv = *(const float4*)(Bptr + (size_t)k0*N);
        As[a_col+0][a_row] = av.x; As[a_col+1][a_row] = av.y;
        As[a_col+2][a_row] = av.z; As[a_col+3][a_row] = av.w;
        *(float4*)&Bs[b_row][b_col] = bv;
        __syncthreads();
        #pragma unroll
        for (int k = 0; k < 8; k++) {
            float4 a0 = *(const float4*)&As[k][ty*8];
            float4 a1 = *(const float4*)&As[k][ty*8+4];
            float4 b0 = *(const float4*)&Bs[k][tx*8];
            float4 b1 = *(const float4*)&Bs[k][tx*8+4];
            float af[8] = {a0.x,a0.y,a0.z,a0.w,a1.x,a1.y,a1.z,a1.w};
            float bf[8] = {b0.x,b0.y,b0.z,b0.w,b1.x,b1.y,b1.z,b1.w};
            #pragma unroll
            for (int i = 0; i < 8; i++)
                #pragma unroll
                for (int j = 0; j < 8; j++)
                    acc[i][j] += af[i]*bf[j];
        }
        __syncthreads();
    }
    #pragma unroll
    for (int i = 0; i < 8; i++) {
        int m = bm*128 + ty*8 + i;
        #pragma unroll
        for (int j = 0; j < 8; j++) {
            int n = bn*128 + tx*8 + j;
            C[(size_t)m*N + n] = acc[i][j] + bias[n];
        }
    }
}
__global__ __launch_bounds__(256) void simt_gemm2_partial(const float* W, const float* bias){
    int bm = blockIdx.y ? 17 : 0;
    simt_gemm2_body(W, bias, bm, blockIdx.x, g_sm);
}
__global__ __launch_bounds__(256) void simt_gemm2_full(const float* W, const float* bias){
    if ((g_f[0] | g_f[1] | g_f[2] | g_f[3] | g_f[4]) == 0) return;
    simt_gemm2_body(W, bias, blockIdx.y, blockIdx.x, g_sm);
}

// ---------------- HMMA GEMM2 -> g_hm ---------------------------------------
__global__ __launch_bounds__(256) void hmma_gemm2(
    const __nv_bfloat16* __restrict__ Ah, const __nv_bfloat16* __restrict__ Al,
    const __nv_bfloat16* __restrict__ Bh, const __nv_bfloat16* __restrict__ Bl,
    const float* __restrict__ bias)
{
    __shared__ __align__(16) __nv_bfloat16 shA[2][128*40];
    __shared__ __align__(16) __nv_bfloat16 shB[2][128*40];
    __shared__ float sh_bias[128];
    int tid = threadIdx.x, lane = tid & 31, wid = tid >> 5;
    int wm = wid >> 2, wn = wid & 3;
    int m0 = blockIdx.y * 128, n0 = blockIdx.x * 128;
    if (tid < 128) sh_bias[tid] = bias[n0 + tid];
    const __nv_bfloat16* srcs[4] = { Ah + (size_t)m0*1024, Al + (size_t)m0*1024,
                                     Bh + (size_t)n0*1024, Bl + (size_t)n0*1024 };
    __nv_bfloat16* dsts[4] = { shA[0], shA[1], shB[0], shB[1] };
    float acc[4][4][4];
    #pragma unroll
    for (int a = 0; a < 4; a++)
        #pragma unroll
        for (int b = 0; b < 4; b++)
            #pragma unroll
            for (int c = 0; c < 4; c++) acc[a][b][c] = 0.f;
    uint32_t uA[2] = { smem_u32(shA[0]), smem_u32(shA[1]) };
    uint32_t uB[2] = { smem_u32(shB[0]), smem_u32(shB[1]) };
    uint32_t mi = lane >> 3, l7 = lane & 7;
    uint32_t a_row = l7 + (mi & 1)*8, a_k = (mi >> 1)*16;
    uint32_t b_row = l7 + (mi >> 1)*8, b_k = (mi & 1)*16;
    for (int s = 0; s < 32; s++){
        __syncthreads();
        #pragma unroll
        for (int i = 0; i < 8; i++){
            int idx = tid + i*256;
            int part = idx >> 9;
            int r = (idx >> 2) & 127, c = idx & 3;
            *(uint4*)(dsts[part] + r*40 + c*8) =
                *(const uint4*)(srcs[part] + (size_t)r*1024 + s*32 + c*8);
        }
        __syncthreads();
        #pragma unroll
        for (int k16 = 0; k16 < 2; k16++){
            uint32_t af[2][4][4], bf2[2][4][2];
            #pragma unroll
            for (int h = 0; h < 2; h++){
                #pragma unroll
                for (int mt = 0; mt < 4; mt++)
                    ldm4(af[h][mt], uA[h] + (wm*64 + mt*16 + a_row)*80 + a_k + k16*32);
                #pragma unroll
                for (int np = 0; np < 2; np++){
                    uint32_t x[4];
                    ldm4(x, uB[h] + (wn*32 + np*16 + b_row)*80 + b_k + k16*32);
                    bf2[h][np*2  ][0]=x[0]; bf2[h][np*2  ][1]=x[1];
                    bf2[h][np*2+1][0]=x[2]; bf2[h][np*2+1][1]=x[3];
                }
            }
            #pragma unroll
            for (int mt = 0; mt < 4; mt++)
                #pragma unroll
                for (int nt = 0; nt < 4; nt++){
                    mma16816(acc[mt][nt], af[0][mt], bf2[0][nt]);
                    mma16816(acc[mt][nt], af[0][mt], bf2[1][nt]);
                    mma16816(acc[mt][nt], af[1][mt], bf2[0][nt]);
                }
        }
    }
    int gid = lane >> 2, tig = lane & 3;
    #pragma unroll
    for (int mt = 0; mt < 4; mt++)
        #pragma unroll
        for (int nt = 0; nt < 4; nt++){
            int nl = wn*32 + nt*8 + tig*2;
            int mg = m0 + wm*64 + mt*16 + gid;
            float2 v0 = make_float2(acc[mt][nt][0] + sh_bias[nl], acc[mt][nt][1] + sh_bias[nl+1]);
            float2 v1 = make_float2(acc[mt][nt][2] + sh_bias[nl], acc[mt][nt][3] + sh_bias[nl+1]);
            *(float2*)(g_hm + (size_t)mg*1024 + n0 + nl) = v0;
            *(float2*)(g_hm + (size_t)(mg+8)*1024 + n0 + nl) = v1;
        }
}

// ---------------- P4: judge + select ---------------------------------------
__global__ __launch_bounds__(256) void p4_judge(){
    int i = blockIdx.x*256 + threadIdx.x;
    int half = i >> 17;
    int r = (i >> 10) & 127, c = i & 1023;
    int m = half ? (17*128 + r) : r;
    float a = g_hm[(size_t)m*1024 + c], b = g_sm[(size_t)m*1024 + c];
    if (fabsf(a - b) > 2e-3f*fmaxf(fabsf(b), 1.f)) atomicExch(&g_f[4], 1);
}
__global__ __launch_bounds__(256) void select_kernel(float* __restrict__ out){
    bool ok = (g_f[0] | g_f[1] | g_f[2] | g_f[3] | g_f[4]) == 0;
    size_t i = (size_t)(blockIdx.x*256 + threadIdx.x) * 4;
    float4 v = ok ? *(const float4*)(g_hm + i) : *(const float4*)(g_sm + i);
    *(float4*)(out + i) = v;
}

// ---------------- launch ----------------------------------------------------
extern "C" void kernel_launch(void* const* d_in, const int* in_sizes, int n_in,
                              void* d_out, int out_size)
{
    const float* x     = (const float*)d_in[0];
    const float* w_qkv = (const float*)d_in[1];
    const float* b_qkv = (const float*)d_in[2];
    const float* w_out = (const float*)d_in[3];
    const float* b_out = (const float*)d_in[4];
    float* out = (float*)d_out;

    reset_kernel<<<1, 1>>>();

    // known-good SIMT front end
    qkv_gemm_kernel<<<dim3(3*H_/128, M_/128), 256>>>(x, w_qkv, b_qkv);
    attn_kernel<<<dim3(S_/QB, B_*NH_), 64>>>();

    // P0: raw bf16 device-global round-trip (before split overwrites g_aoh)
    p0_write<<<128, 256>>>();
    p0_check<<<128, 256>>>();

    // prep + P1
    split_kernel<<<M_*H_/1024, 256>>>(g_ao, g_aoh, g_aol);
    tr_split_kernel<<<dim3(H_/32, H_/32), 256>>>(w_out, H_, g_woth, g_wotl);
    p1_check<<<16, 256>>>(w_out);

    // P2 / P3: primitive KATs
    p2_ldm<<<1, 32>>>();
    p3_mma<<<1, 32>>>();

    // HMMA GEMM2 + P4 judge against SIMT partial
    hmma_gemm2<<<dim3(8, 32), 256>>>(g_aoh, g_aol, g_woth, g_wotl, b_out);
    simt_gemm2_partial<<<dim3(8, 2), 256>>>(w_out, b_out);
    p4_judge<<<1024, 256>>>();
    simt_gemm2_full<<<dim3(8, 32), 256>>>(w_out, b_out);   // early-exits if all clear

    // output + priority-encoded diagnosis burn
    select_kernel<<<M_*H_/4/256, 256>>>(out);
    burn_kernel<<<1, 32>>>();
}

// round 14
// speedup vs baseline: 25.5947x; 25.5947x over previous
#include <cuda_runtime.h>
#include <cuda_bf16.h>
#include <cstdint>

#define B_   2
#define S_   2048
#define H_   1024
#define NH_  16
#define HD_  64
#define M_   (B_*S_)
#define SCALE_ 0.125f

// -------- device scratch: NEVER passed as kernel arguments -----------------
__device__ __align__(16) __nv_bfloat16 g_xh [M_*H_],     g_xl [M_*H_];
__device__ __align__(16) __nv_bfloat16 g_wqth[3*H_*H_],  g_wqtl[3*H_*H_];  // Wqkv^T [3072][1024]
__device__ __align__(16) __nv_bfloat16 g_woth[H_*H_],    g_wotl[H_*H_];    // Wout^T [1024][1024]
__device__ __align__(16) __nv_bfloat16 g_qh [32*S_*HD_], g_ql [32*S_*HD_]; // [bh][s][d]
__device__ __align__(16) __nv_bfloat16 g_kh [32*S_*HD_], g_kl [32*S_*HD_]; // [bh][s][d]
__device__ __align__(16) __nv_bfloat16 g_vth[32*HD_*S_], g_vtl[32*HD_*S_]; // [bh][d][s]
__device__ __align__(16) __nv_bfloat16 g_aoh[M_*H_],     g_aol[M_*H_];     // attn out [m][1024]

// ---------------- helpers ---------------------------------------------------
__device__ __forceinline__ uint32_t smem_u32(const void* p){
    uint32_t a;
    asm("{ .reg .u64 t; cvta.to.shared.u64 t, %1; cvt.u32.u64 %0, t; }" : "=r"(a) : "l"(p));
    return a;
}
__device__ __forceinline__ void split2(float v, __nv_bfloat16& h, __nv_bfloat16& l){
    h = __float2bfloat16(v);
    l = __float2bfloat16(v - __bfloat162float(h));
}
__device__ __forceinline__ uint32_t bfpair(__nv_bfloat16 a, __nv_bfloat16 b){
    return (uint32_t)__bfloat16_as_ushort(a) | ((uint32_t)__bfloat16_as_ushort(b) << 16);
}
__device__ __forceinline__ void mma16816(float* c, const uint32_t* a, const uint32_t* b){
    asm volatile("mma.sync.aligned.m16n8k16.row.col.f32.bf16.bf16.f32 "
        "{%0,%1,%2,%3}, {%4,%5,%6,%7}, {%8,%9}, {%0,%1,%2,%3};"
        : "+f"(c[0]), "+f"(c[1]), "+f"(c[2]), "+f"(c[3])
        : "r"(a[0]), "r"(a[1]), "r"(a[2]), "r"(a[3]), "r"(b[0]), "r"(b[1]));
}
__device__ __forceinline__ void ldm4(uint32_t* r, uint32_t addr){
    asm volatile("ldmatrix.sync.aligned.m8n8.x4.shared.b16 {%0,%1,%2,%3}, [%4];"
        : "=r"(r[0]), "=r"(r[1]), "=r"(r[2]), "=r"(r[3]) : "r"(addr));
}

// ---------------- prep: x -> hi/lo (dst = device globals, direct) ----------
__global__ __launch_bounds__(256) void split_x_kernel(const float* __restrict__ src){
    int i4 = (blockIdx.x*256 + threadIdx.x) * 4;
    float4 v = *(const float4*)(src + i4);
    __nv_bfloat16 h0,l0,h1,l1,h2,l2,h3,l3;
    split2(v.x,h0,l0); split2(v.y,h1,l1); split2(v.z,h2,l2); split2(v.w,h3,l3);
    *(uint2*)(g_xh + i4) = make_uint2(bfpair(h0,h1), bfpair(h2,h3));
    *(uint2*)(g_xl + i4) = make_uint2(bfpair(l0,l1), bfpair(l2,l3));
}
// transpose + split: sel 0 -> Wqkv^T (C=3072), sel 1 -> Wout^T (C=1024)
__global__ __launch_bounds__(256) void tr_split_kernel(const float* __restrict__ src,
                                                       int C, int sel){
    __nv_bfloat16* dh = sel ? g_woth : g_wqth;
    __nv_bfloat16* dl = sel ? g_wotl : g_wqtl;
    __shared__ float ts[32][33];
    int tx = threadIdx.x & 31, ty = threadIdx.x >> 5;      // 32x8
    int c0 = blockIdx.x*32, r0 = blockIdx.y*32;
    #pragma unroll
    for (int i = 0; i < 4; i++)
        ts[ty + i*8][tx] = src[(size_t)(r0 + ty + i*8)*C + c0 + tx];
    __syncthreads();
    #pragma unroll
    for (int i = 0; i < 4; i++){
        float v = ts[tx][ty + i*8];
        __nv_bfloat16 h,l; split2(v,h,l);
        size_t o = (size_t)(c0 + ty + i*8)*1024 + r0 + tx;  // [n][k], k stride 1024
        dh[o] = h; dl[o] = l;
    }
}

// ---------------- HMMA GEMM: 128x128 block, BK=32, K=1024, static smem -----
// mode 0: A=g_xh/l, B=g_wqth/l, scatter bf16 hi/lo to q/k/v(T)
// mode 1: A=g_aoh/l, B=g_woth/l, fp32 store + bias to Cout
__global__ __launch_bounds__(256) void hmma_gemm(
    const float* __restrict__ bias, float* __restrict__ Cout, int mode)
{
    __shared__ __align__(16) __nv_bfloat16 shA[2][128*40];   // hi/lo, 80B row stride
    __shared__ __align__(16) __nv_bfloat16 shB[2][128*40];
    __shared__ float sh_bias[128];

    int tid = threadIdx.x, lane = tid & 31, wid = tid >> 5;
    int wm = wid >> 2, wn = wid & 3;                 // 2x4 warps -> 64x32 tiles
    int m0 = blockIdx.y * 128, n0 = blockIdx.x * 128;
    if (tid < 128) sh_bias[tid] = bias[n0 + tid];

    const __nv_bfloat16* srcs[4] = {
        (mode == 0 ? g_xh  : g_aoh) + (size_t)m0*1024,
        (mode == 0 ? g_xl  : g_aol) + (size_t)m0*1024,
        (mode == 0 ? g_wqth: g_woth) + (size_t)n0*1024,
        (mode == 0 ? g_wqtl: g_wotl) + (size_t)n0*1024 };
    __nv_bfloat16* dsts[4] = { shA[0], shA[1], shB[0], shB[1] };

    float acc[4][4][4];
    #pragma unroll
    for (int a = 0; a < 4; a++)
        #pragma unroll
        for (int b = 0; b < 4; b++)
            #pragma unroll
            for (int c = 0; c < 4; c++) acc[a][b][c] = 0.f;

    uint32_t uA[2] = { smem_u32(shA[0]), smem_u32(shA[1]) };
    uint32_t uB[2] = { smem_u32(shB[0]), smem_u32(shB[1]) };

    uint32_t mi = lane >> 3, l7 = lane & 7;
    uint32_t a_row = l7 + (mi & 1)*8, a_k = (mi >> 1)*16;   // bytes
    uint32_t b_row = l7 + (mi >> 1)*8, b_k = (mi & 1)*16;   // bytes

    for (int s = 0; s < 32; s++){
        __syncthreads();
        #pragma unroll
        for (int i = 0; i < 8; i++){
            int idx = tid + i*256;
            int part = idx >> 9;
            int r = (idx >> 2) & 127, c = idx & 3;
            *(uint4*)(dsts[part] + r*40 + c*8) =
                *(const uint4*)(srcs[part] + (size_t)r*1024 + s*32 + c*8);
        }
        __syncthreads();
        #pragma unroll
        for (int k16 = 0; k16 < 2; k16++){
            uint32_t af[2][4][4], bf2[2][4][2];
            #pragma unroll
            for (int h = 0; h < 2; h++){
                #pragma unroll
                for (int mt = 0; mt < 4; mt++)
                    ldm4(af[h][mt], uA[h] + (wm*64 + mt*16 + a_row)*80 + a_k + k16*32);
                #pragma unroll
                for (int np = 0; np < 2; np++){
                    uint32_t x[4];
                    ldm4(x, uB[h] + (wn*32 + np*16 + b_row)*80 + b_k + k16*32);
                    bf2[h][np*2  ][0]=x[0]; bf2[h][np*2  ][1]=x[1];
                    bf2[h][np*2+1][0]=x[2]; bf2[h][np*2+1][1]=x[3];
                }
            }
            #pragma unroll
            for (int mt = 0; mt < 4; mt++)
                #pragma unroll
                for (int nt = 0; nt < 4; nt++){
                    mma16816(acc[mt][nt], af[0][mt], bf2[0][nt]);
                    mma16816(acc[mt][nt], af[0][mt], bf2[1][nt]);
                    mma16816(acc[mt][nt], af[1][mt], bf2[0][nt]);
                }
        }
    }

    int gid = lane >> 2, tig = lane & 3;
    if (mode == 1){
        #pragma unroll
        for (int mt = 0; mt < 4; mt++)
            #pragma unroll
            for (int nt = 0; nt < 4; nt++){
                int nl = wn*32 + nt*8 + tig*2;
                int mg = m0 + wm*64 + mt*16 + gid;
                float2 v0 = make_float2(acc[mt][nt][0] + sh_bias[nl], acc[mt][nt][1] + sh_bias[nl+1]);
                float2 v1 = make_float2(acc[mt][nt][2] + sh_bias[nl], acc[mt][nt][3] + sh_bias[nl+1]);
                *(float2*)(Cout + (size_t)mg*1024 + n0 + nl) = v0;
                *(float2*)(Cout + (size_t)(mg+8)*1024 + n0 + nl) = v1;
            }
    } else {
        #pragma unroll
        for (int mt = 0; mt < 4; mt++)
            #pragma unroll
            for (int nt = 0; nt < 4; nt++)
                #pragma unroll
                for (int hf = 0; hf < 2; hf++){
                    int mg = m0 + wm*64 + mt*16 + gid + hf*8;
                    int bb = mg >> 11, ss = mg & 2047;
                    int nl = wn*32 + nt*8 + tig*2;
                    int n = n0 + nl;
                    float v0 = acc[mt][nt][hf*2+0] + sh_bias[nl];
                    float v1 = acc[mt][nt][hf*2+1] + sh_bias[nl+1];
                    __nv_bfloat16 h0,l0,h1,l1;
                    split2(v0,h0,l0); split2(v1,h1,l1);
                    int which = n >> 10, hh = (n & 1023) >> 6, dd = n & 63;
                    int bh = bb*16 + hh;
                    if (which == 0){
                        size_t ix = ((size_t)bh*2048 + ss)*64 + dd;
                        *(uint32_t*)(g_qh + ix) = bfpair(h0,h1);
                        *(uint32_t*)(g_ql + ix) = bfpair(l0,l1);
                    } else if (which == 1){
                        size_t ix = ((size_t)bh*2048 + ss)*64 + dd;
                        *(uint32_t*)(g_kh + ix) = bfpair(h0,h1);
                        *(uint32_t*)(g_kl + ix) = bfpair(l0,l1);
                    } else {
                        size_t ix = (size_t)bh*131072 + (size_t)dd*2048 + ss;
                        g_vth[ix] = h0;      g_vtl[ix] = l0;
                        g_vth[ix+2048] = h1; g_vtl[ix+2048] = l1;
                    }
                }
    }
}

// ---------------- HMMA flash attention: 64 q rows, 4 warps, static smem ----
__global__ __launch_bounds__(128) void hmma_attn()
{
    __shared__ __align__(16) __nv_bfloat16 sQ[2][64*72];   // 144B row stride
    __shared__ __align__(16) __nv_bfloat16 sK[2][32*72];
    __shared__ __align__(16) __nv_bfloat16 sV[2][64*40];   // V^T: [d][j], 80B stride

    int tid = threadIdx.x, lane = tid & 31, wid = tid >> 5;   // 4 warps
    int qt = blockIdx.x, bh = blockIdx.y;                      // 32 x 32
    size_t hb = (size_t)bh * 131072;

    // Q load (once): 64 rows x 64 d, hi/lo
    #pragma unroll
    for (int i = 0; i < 8; i++){
        int idx = tid + i*128;
        int h = idx >> 9, r = (idx >> 3) & 63, c = idx & 7;
        const __nv_bfloat16* src = (h ? g_ql : g_qh) + hb + (size_t)(qt*64 + r)*64 + c*8;
        *(uint4*)(sQ[h] + r*72 + c*8) = *(const uint4*)src;
    }

    uint32_t uQ[2] = { smem_u32(sQ[0]), smem_u32(sQ[1]) };
    uint32_t uK[2] = { smem_u32(sK[0]), smem_u32(sK[1]) };
    uint32_t uV[2] = { smem_u32(sV[0]), smem_u32(sV[1]) };

    uint32_t mi = lane >> 3, l7 = lane & 7;
    uint32_t a_row = l7 + (mi & 1)*8, a_k = (mi >> 1)*16;
    uint32_t b_row = l7 + (mi >> 1)*8, b_k = (mi & 1)*16;

    uint32_t qa[2][4][4];
    bool qloaded = false;
    float oacc[8][4];
    #pragma unroll
    for (int i = 0; i < 8; i++)
        #pragma unroll
        for (int c = 0; c < 4; c++) oacc[i][c] = 0.f;
    float ls0 = 0.f, ls1 = 0.f, m0 = -1e30f, m1 = -1e30f;

    for (int kb = 0; kb < 64; kb++){
        __syncthreads();
        // K tile: 32 rows x 64 d hi/lo
        #pragma unroll
        for (int i = 0; i < 4; i++){
            int idx = tid + i*128;
            int h = idx >> 8, r = (idx >> 3) & 31, c = idx & 7;
            const __nv_bfloat16* src = (h ? g_kl : g_kh) + hb + (size_t)(kb*32 + r)*64 + c*8;
            *(uint4*)(sK[h] + r*72 + c*8) = *(const uint4*)src;
        }
        // V^T tile: 64 d-rows x 32 keys hi/lo
        #pragma unroll
        for (int i = 0; i < 4; i++){
            int idx = tid + i*128;
            int h = idx >> 8, r = (idx >> 2) & 63, c = idx & 3;
            const __nv_bfloat16* src = (h ? g_vtl : g_vth) + hb + (size_t)r*2048 + kb*32 + c*8;
            *(uint4*)(sV[h] + r*40 + c*8) = *(const uint4*)src;
        }
        __syncthreads();
        if (!qloaded){
            qloaded = true;
            #pragma unroll
            for (int h = 0; h < 2; h++)
                #pragma unroll
                for (int k16 = 0; k16 < 4; k16++)
                    ldm4(qa[h][k16], uQ[h] + (wid*16 + a_row)*144 + a_k + k16*32);
        }
        // ---- S = Q K^T (3-term hi/lo) ----
        float sacc[4][4];
        #pragma unroll
        for (int nt = 0; nt < 4; nt++)
            #pragma unroll
            for (int c = 0; c < 4; c++) sacc[nt][c] = 0.f;
        #pragma unroll
        for (int k16 = 0; k16 < 4; k16++){
            uint32_t kf[2][4][2];
            #pragma unroll
            for (int h = 0; h < 2; h++)
                #pragma unroll
                for (int np = 0; np < 2; np++){
                    uint32_t x[4];
                    ldm4(x, uK[h] + (np*16 + b_row)*144 + b_k + k16*32);
                    kf[h][np*2  ][0]=x[0]; kf[h][np*2  ][1]=x[1];
                    kf[h][np*2+1][0]=x[2]; kf[h][np*2+1][1]=x[3];
                }
            #pragma unroll
            for (int nt = 0; nt < 4; nt++){
                mma16816(sacc[nt], qa[0][k16], kf[0][nt]);
                mma16816(sacc[nt], qa[0][k16], kf[1][nt]);
                mma16816(sacc[nt], qa[1][k16], kf[0][nt]);
            }
        }
        // ---- online-max softmax (overflow impossible) ----
        float sc[4][4];
        float mx0 = -1e30f, mx1 = -1e30f;
        #pragma unroll
        for (int nt = 0; nt < 4; nt++){
            sc[nt][0] = sacc[nt][0]*SCALE_; sc[nt][1] = sacc[nt][1]*SCALE_;
            sc[nt][2] = sacc[nt][2]*SCALE_; sc[nt][3] = sacc[nt][3]*SCALE_;
            mx0 = fmaxf(mx0, fmaxf(sc[nt][0], sc[nt][1]));
            mx1 = fmaxf(mx1, fmaxf(sc[nt][2], sc[nt][3]));
        }
        mx0 = fmaxf(mx0, __shfl_xor_sync(0xffffffffu, mx0, 1));
        mx0 = fmaxf(mx0, __shfl_xor_sync(0xffffffffu, mx0, 2));
        mx1 = fmaxf(mx1, __shfl_xor_sync(0xffffffffu, mx1, 1));
        mx1 = fmaxf(mx1, __shfl_xor_sync(0xffffffffu, mx1, 2));
        float nm0 = fmaxf(m0, mx0), nm1 = fmaxf(m1, mx1);
        float cr0 = __expf(m0 - nm0), cr1 = __expf(m1 - nm1);
        m0 = nm0; m1 = nm1;
        ls0 *= cr0; ls1 *= cr1;
        #pragma unroll
        for (int dnt = 0; dnt < 8; dnt++){
            oacc[dnt][0] *= cr0; oacc[dnt][1] *= cr0;
            oacc[dnt][2] *= cr1; oacc[dnt][3] *= cr1;
        }
        // ---- exp + pack P (C-frag -> A-frag identity) ----
        uint32_t ph[2][4], pl[2][4];
        #pragma unroll
        for (int kc = 0; kc < 2; kc++)
            #pragma unroll
            for (int hf = 0; hf < 2; hf++){
                int nt = kc*2 + hf;
                float p0 = __expf(sc[nt][0] - m0);
                float p1 = __expf(sc[nt][1] - m0);
                float p2 = __expf(sc[nt][2] - m1);
                float p3 = __expf(sc[nt][3] - m1);
                ls0 += p0 + p1; ls1 += p2 + p3;
                __nv_bfloat16 h0,l0,h1,l1,h2,l2,h3,l3;
                split2(p0,h0,l0); split2(p1,h1,l1); split2(p2,h2,l2); split2(p3,h3,l3);
                ph[kc][hf*2+0] = bfpair(h0,h1);
                ph[kc][hf*2+1] = bfpair(h2,h3);
                pl[kc][hf*2+0] = bfpair(l0,l1);
                pl[kc][hf*2+1] = bfpair(l2,l3);
            }
        // ---- O += P V (3-term hi/lo) ----
        #pragma unroll
        for (int kc = 0; kc < 2; kc++)
            #pragma unroll
            for (int dp = 0; dp < 4; dp++){
                uint32_t vf[2][2][2];
                #pragma unroll
                for (int h = 0; h < 2; h++){
                    uint32_t x[4];
                    ldm4(x, uV[h] + (dp*16 + b_row)*80 + b_k + kc*32);
                    vf[h][0][0]=x[0]; vf[h][0][1]=x[1];
                    vf[h][1][0]=x[2]; vf[h][1][1]=x[3];
                }
                #pragma unroll
                for (int t2 = 0; t2 < 2; t2++){
                    int dnt = dp*2 + t2;
                    mma16816(oacc[dnt], ph[kc], vf[0][t2]);
                    mma16816(oacc[dnt], ph[kc], vf[1][t2]);
                    mma16816(oacc[dnt], pl[kc], vf[0][t2]);
                }
            }
    }

    // ---- normalize + store (direct globals) ----
    ls0 += __shfl_xor_sync(0xffffffffu, ls0, 1);
    ls0 += __shfl_xor_sync(0xffffffffu, ls0, 2);
    ls1 += __shfl_xor_sync(0xffffffffu, ls1, 1);
    ls1 += __shfl_xor_sync(0xffffffffu, ls1, 2);
    float inv0 = 1.f/ls0, inv1 = 1.f/ls1;
    int gid = lane >> 2, tig = lane & 3;
    int b = bh >> 4, h = bh & 15;
    size_t m0r = (size_t)b*2048 + qt*64 + wid*16 + gid;
    #pragma unroll
    for (int dnt = 0; dnt < 8; dnt++){
        int col = h*64 + dnt*8 + tig*2;
        float v0 = oacc[dnt][0]*inv0, v1 = oacc[dnt][1]*inv0;
        float v2 = oacc[dnt][2]*inv1, v3 = oacc[dnt][3]*inv1;
        __nv_bfloat16 a0,c0,a1,c1,a2,c2,a3,c3;
        split2(v0,a0,c0); split2(v1,a1,c1); split2(v2,a2,c2); split2(v3,a3,c3);
        *(uint32_t*)(g_aoh + m0r*1024 + col)     = bfpair(a0,a1);
        *(uint32_t*)(g_aol + m0r*1024 + col)     = bfpair(c0,c1);
        *(uint32_t*)(g_aoh + (m0r+8)*1024 + col) = bfpair(a2,a3);
        *(uint32_t*)(g_aol + (m0r+8)*1024 + col) = bfpair(c2,c3);
    }
}

// ---------------- launch ----------------------------------------------------
extern "C" void kernel_launch(void* const* d_in, const int* in_sizes, int n_in,
                              void* d_out, int out_size)
{
    const float* x     = (const float*)d_in[0];
    const float* w_qkv = (const float*)d_in[1];
    const float* b_qkv = (const float*)d_in[2];
    const float* w_out = (const float*)d_in[3];
    const float* b_out = (const float*)d_in[4];
    float* out = (float*)d_out;

    split_x_kernel<<<M_*H_/1024, 256>>>(x);
    tr_split_kernel<<<dim3(3*H_/32, H_/32), 256>>>(w_qkv, 3*H_, 0);
    tr_split_kernel<<<dim3(H_/32,   H_/32), 256>>>(w_out,  H_,  1);

    hmma_gemm<<<dim3(24, 32), 256>>>(b_qkv, nullptr, 0);   // qkv proj + scatter
    hmma_attn<<<dim3(32, 32), 128>>>();                    // flash attention
    hmma_gemm<<<dim3(8, 32), 256>>>(b_out, out, 1);        // output proj
}